// round 8
// baseline (speedup 1.0000x reference)
#include <cuda_runtime.h>
#include <cuda_bf16.h>
#include <cstdint>
#include <math.h>

// Problem constants
#define Nn   50000
#define Ee   800000
#define Fdim 128
#define Gn   64
#define OUTC 64
#define EXPN 3
#define TEMP_INV (1.0f/101.0f)

#define SCAN_B 1024
#define NBLK   ((Nn + SCAN_B - 1) / SCAN_B)

// A-tile smem row stride in bytes (128 bf16 = 256B, padded to 272)
#define AROW 272
#define ABYTES (128 * AROW)
#define DYN_SMEM (2 * ABYTES)

// ---------------- device scratch ----------------
__device__ float g_dinv[Nn];
__device__ int   g_degi[Nn];
__device__ int   g_off [Nn + 1];
__device__ int   g_cur [Nn];
__device__ int   g_bsum[NBLK];
__device__ int   g_csr [Ee];
__device__ float g_h  [(size_t)Nn * Fdim];   // layer-0 output
__device__ float g_h2 [(size_t)Nn * Fdim];   // layer-1 output
// packed W fragments: [e(3)][kk(8)][ntg(16)][lane(32)] -> uint2 {b0,b1}
__device__ uint2 g_wph0[12288];
__device__ uint2 g_wpl0[12288];
__device__ uint2 g_wph1[12288];
__device__ uint2 g_wpl1[12288];

// ---------------- helpers ----------------
__device__ __forceinline__ void split2(float a, float b, uint32_t& hi, uint32_t& lo) {
    __nv_bfloat162 h = __floats2bfloat162_rn(a, b);
    float ra = a - __bfloat162float(h.x);
    float rb = b - __bfloat162float(h.y);
    __nv_bfloat162 l = __floats2bfloat162_rn(ra, rb);
    hi = *reinterpret_cast<uint32_t*>(&h);
    lo = *reinterpret_cast<uint32_t*>(&l);
}
__device__ __forceinline__ uint32_t smem_u32(const void* p) {
    uint32_t a;
    asm("{ .reg .u64 t; cvta.to.shared.u64 t, %1; cvt.u32.u64 %0, t; }" : "=r"(a) : "l"(p));
    return a;
}
__device__ __forceinline__ void ldsm4(uint32_t* r, uint32_t addr) {
    asm volatile("ldmatrix.sync.aligned.m8n8.x4.shared.b16 {%0,%1,%2,%3}, [%4];"
        : "=r"(r[0]), "=r"(r[1]), "=r"(r[2]), "=r"(r[3]) : "r"(addr));
}
__device__ __forceinline__ void mma16816(float* d, const uint32_t* a, uint2 b) {
    asm volatile("mma.sync.aligned.m16n8k16.row.col.f32.bf16.bf16.f32 "
        "{%0,%1,%2,%3}, {%4,%5,%6,%7}, {%8,%9}, {%0,%1,%2,%3};"
        : "+f"(d[0]), "+f"(d[1]), "+f"(d[2]), "+f"(d[3])
        : "r"(a[0]), "r"(a[1]), "r"(a[2]), "r"(a[3]), "r"(b.x), "r"(b.y));
}

// ---------------- CSR build ----------------
__global__ void k_init() {
    int i = blockIdx.x * blockDim.x + threadIdx.x;
    if (i < Nn) g_degi[i] = 0;
}
__global__ void k_count(const int* __restrict__ dst) {
    int e = blockIdx.x * blockDim.x + threadIdx.x;
    if (e < Ee) atomicAdd(&g_degi[dst[e]], 1);
}
__global__ void k_scan1() {      // block scan + fused rsqrt
    __shared__ int s[SCAN_B];
    int b = blockIdx.x, t = threadIdx.x;
    int i = b * SCAN_B + t;
    int v = (i < Nn) ? g_degi[i] : 0;
    if (i < Nn) g_dinv[i] = rsqrtf((float)(v + 1));   // +1 self loop
    s[t] = v;
    __syncthreads();
    for (int d = 1; d < SCAN_B; d <<= 1) {
        int add = (t >= d) ? s[t - d] : 0;
        __syncthreads();
        s[t] += add;
        __syncthreads();
    }
    if (i < Nn) g_off[i] = s[t] - v;
    if (t == SCAN_B - 1) g_bsum[b] = s[t];
}
__global__ void k_scan2() {
    if (threadIdx.x == 0) {
        int run = 0;
        for (int b = 0; b < NBLK; b++) { int v = g_bsum[b]; g_bsum[b] = run; run += v; }
        g_off[Nn] = Ee;
    }
}
__global__ void k_scan3() {
    int i = blockIdx.x * blockDim.x + threadIdx.x;
    if (i < Nn) {
        int o = g_off[i] + g_bsum[i / SCAN_B];
        g_off[i] = o;
        g_cur[i] = o;
    }
}
__global__ void k_fill(const int* __restrict__ src, const int* __restrict__ dst) {
    int e = blockIdx.x * blockDim.x + threadIdx.x;
    if (e < Ee) {
        int pos = atomicAdd(&g_cur[dst[e]], 1);
        g_csr[pos] = src[e];
    }
}

// ---------------- W fragment packing (both layers) ----------------
__global__ void k_wsplit2(const float* __restrict__ W0, const float* __restrict__ W1) {
    int gidx = blockIdx.x * blockDim.x + threadIdx.x;
    if (gidx >= 24576) return;
    int layer = (gidx >= 12288) ? 1 : 0;
    int idx   = gidx - layer * 12288;
    int lane = idx & 31;
    int ntg  = (idx >> 5) & 15;
    int kk   = (idx >> 9) & 7;
    int e    = idx >> 12;
    int n  = ntg * 8 + (lane >> 2);
    int k0 = kk * 16 + (lane & 3) * 2;
    const float* We = (layer ? W1 : W0) + (size_t)e * Fdim * Fdim;
    uint32_t h0, l0, h1, l1;
    split2(We[(size_t)k0 * Fdim + n],       We[(size_t)(k0 + 1) * Fdim + n], h0, l0);
    split2(We[(size_t)(k0 + 8) * Fdim + n], We[(size_t)(k0 + 9) * Fdim + n], h1, l1);
    uint2* ph = layer ? g_wph1 : g_wph0;
    uint2* pl = layer ? g_wpl1 : g_wpl0;
    ph[idx] = make_uint2(h0, h1);
    pl[idx] = make_uint2(l0, l1);
}

// ---------------- fused gather + MoE GEMM ----------------
// 512 threads, 128-node tile. Phase 1: per-warp CSR gather of 8 rows each,
// dinv scaling, bf16 hi/lo split straight into smem. Phase 2: mma.sync.
extern __shared__ char dynA[];   // [A_hi 34816][A_lo 34816]
__global__ __launch_bounds__(512)
void k_gemm_fused(const float* __restrict__ xin, int layer,
                  const float* __restrict__ bvec, // [3,128]
                  const float* __restrict__ Wg,   // [3,4]
                  const float* __restrict__ top)  // [N,4]
{
    __shared__ float sgate[128][4];

    int tid  = threadIdx.x;
    int m0   = blockIdx.x * 128;
    int w    = tid >> 5;
    int lane = tid & 31;

    const float* inp = layer ? (const float*)g_h : xin;
    const float4* P  = (const float4*)inp;

    // ---- gates ----
    if (tid < 128) {
        int n = m0 + tid;
        float l0 = 0.f, l1 = 0.f, l2 = 0.f;
        if (n < Nn) {
            float t0 = top[n*4+0], t1 = top[n*4+1], t2 = top[n*4+2], t3 = top[n*4+3];
            l0 = (t0*Wg[0] + t1*Wg[1] + t2*Wg[2]  + t3*Wg[3])  * TEMP_INV;
            l1 = (t0*Wg[4] + t1*Wg[5] + t2*Wg[6]  + t3*Wg[7])  * TEMP_INV;
            l2 = (t0*Wg[8] + t1*Wg[9] + t2*Wg[10] + t3*Wg[11]) * TEMP_INV;
        }
        float mx = fmaxf(l0, fmaxf(l1, l2));
        float e0 = __expf(l0 - mx), e1 = __expf(l1 - mx), e2 = __expf(l2 - mx);
        float inv = 1.0f / (e0 + e1 + e2);
        sgate[tid][0] = e0 * inv; sgate[tid][1] = e1 * inv; sgate[tid][2] = e2 * inv;
    }

    // ---- phase 1: gather + split. warp w handles rows [w*8, w*8+8) ----
    for (int r = 0; r < 8; r++) {
        int row = w * 8 + r;
        int n   = m0 + row;
        float4 acc = make_float4(0.f, 0.f, 0.f, 0.f);
        if (n < Nn) {
            float dn = g_dinv[n];
            float4 v = P[(size_t)n * 32 + lane];
            acc.x = dn * v.x; acc.y = dn * v.y; acc.z = dn * v.z; acc.w = dn * v.w;
            int e   = g_off[n];
            int end = g_off[n + 1];
            for (; e + 4 <= end; e += 4) {
                int s0 = g_csr[e],   s1 = g_csr[e+1];
                int s2 = g_csr[e+2], s3 = g_csr[e+3];
                float d0 = g_dinv[s0], d1 = g_dinv[s1], d2 = g_dinv[s2], d3 = g_dinv[s3];
                float4 v0 = P[(size_t)s0 * 32 + lane];
                float4 v1 = P[(size_t)s1 * 32 + lane];
                float4 v2 = P[(size_t)s2 * 32 + lane];
                float4 v3 = P[(size_t)s3 * 32 + lane];
                acc.x += d0*v0.x + d1*v1.x + d2*v2.x + d3*v3.x;
                acc.y += d0*v0.y + d1*v1.y + d2*v2.y + d3*v3.y;
                acc.z += d0*v0.z + d1*v1.z + d2*v2.z + d3*v3.z;
                acc.w += d0*v0.w + d1*v1.w + d2*v2.w + d3*v3.w;
            }
            for (; e < end; e++) {
                int s = g_csr[e];
                float ds = g_dinv[s];
                float4 vv = P[(size_t)s * 32 + lane];
                acc.x += ds*vv.x; acc.y += ds*vv.y; acc.z += ds*vv.z; acc.w += ds*vv.w;
            }
            acc.x *= dn; acc.y *= dn; acc.z *= dn; acc.w *= dn;
        }
        uint32_t h0, l0, h1, l1;
        split2(acc.x, acc.y, h0, l0);
        split2(acc.z, acc.w, h1, l1);
        char* base = dynA + row * AROW + lane * 8;
        *reinterpret_cast<uint32_t*>(base)              = h0;
        *reinterpret_cast<uint32_t*>(base + 4)          = h1;
        *reinterpret_cast<uint32_t*>(base + ABYTES)     = l0;
        *reinterpret_cast<uint32_t*>(base + ABYTES + 4) = l1;
    }
    __syncthreads();

    // ---- phase 2: MMA ----
    int wm = w & 3;
    int wn = w >> 2;

    uint32_t aBase  = smem_u32(dynA);
    uint32_t aAddr0 = aBase + (uint32_t)(wm * 32 + (lane & 15)) * AROW + (uint32_t)(lane >> 4) * 16;

    const uint2* wph = layer ? g_wph1 : g_wph0;
    const uint2* wpl = layer ? g_wpl1 : g_wpl0;

    float out[2][4][4];
    #pragma unroll
    for (int mt = 0; mt < 2; mt++)
        #pragma unroll
        for (int nt = 0; nt < 4; nt++)
            #pragma unroll
            for (int rr = 0; rr < 4; rr++) out[mt][nt][rr] = 0.f;

    int r0 = wm * 32 + (lane >> 2);

    for (int e = 0; e < EXPN; e++) {
        float acc[2][4][4];
        #pragma unroll
        for (int mt = 0; mt < 2; mt++)
            #pragma unroll
            for (int nt = 0; nt < 4; nt++)
                #pragma unroll
                for (int rr = 0; rr < 4; rr++) acc[mt][nt][rr] = 0.f;

        #pragma unroll
        for (int p = 0; p < 3; p++) {
            const uint2* Bp = ((p == 1) ? wpl : wph) + e * 4096 + (wn * 4) * 32 + lane;
            uint32_t aOff = aAddr0 + ((p == 2) ? ABYTES : 0u);
            #pragma unroll
            for (int kk = 0; kk < 8; kk++) {
                uint32_t a0[4], a1[4];
                ldsm4(a0, aOff + kk * 32);
                ldsm4(a1, aOff + kk * 32 + 16 * AROW);
                const uint2* Bk = Bp + kk * 512;
                #pragma unroll
                for (int nt = 0; nt < 4; nt++) {
                    uint2 b = Bk[nt * 32];
                    mma16816(acc[0][nt], a0, b);
                    mma16816(acc[1][nt], a1, b);
                }
            }
        }
        #pragma unroll
        for (int mt = 0; mt < 2; mt++) {
            float gA = sgate[r0 + mt * 16][e];
            float gB = sgate[r0 + mt * 16 + 8][e];
            #pragma unroll
            for (int nt = 0; nt < 4; nt++) {
                float2 bias = *(const float2*)(bvec + e * Fdim + wn * 32 + nt * 8 + (lane & 3) * 2);
                out[mt][nt][0] += gA * fmaxf(acc[mt][nt][0] + bias.x, 0.f);
                out[mt][nt][1] += gA * fmaxf(acc[mt][nt][1] + bias.y, 0.f);
                out[mt][nt][2] += gB * fmaxf(acc[mt][nt][2] + bias.x, 0.f);
                out[mt][nt][3] += gB * fmaxf(acc[mt][nt][3] + bias.y, 0.f);
            }
        }
    }

    float* dstbuf = layer ? g_h2 : g_h;
    #pragma unroll
    for (int mt = 0; mt < 2; mt++) {
        int ra = m0 + r0 + mt * 16;
        int rb = ra + 8;
        #pragma unroll
        for (int nt = 0; nt < 4; nt++) {
            int col = wn * 32 + nt * 8 + (lane & 3) * 2;
            if (ra < Nn)
                *(float2*)(dstbuf + (size_t)ra * Fdim + col) = make_float2(out[mt][nt][0], out[mt][nt][1]);
            if (rb < Nn)
                *(float2*)(dstbuf + (size_t)rb * Fdim + col) = make_float2(out[mt][nt][2], out[mt][nt][3]);
        }
    }
}

// ---------------- pool + final linear (one block per graph, batch sorted) ----------------
__device__ __forceinline__ int lbound(const int* __restrict__ b, int val) {
    int lo = 0, hi = Nn;
    while (lo < hi) { int mid = (lo + hi) >> 1; if (b[mid] < val) lo = mid + 1; else hi = mid; }
    return lo;
}
__global__ __launch_bounds__(128)
void k_poolfinal(const int* __restrict__ batch,
                 const float* __restrict__ Wf, const float* __restrict__ bf,
                 float* __restrict__ out) {
    __shared__ float sp[Fdim];
    int g = blockIdx.x;
    int t = threadIdx.x;
    int lo = lbound(batch, g);
    int hi = lbound(batch, g + 1);
    float acc = 0.f;
    for (int n = lo; n < hi; n++) acc += g_h2[(size_t)n * Fdim + t];
    float cnt = (float)(hi - lo);
    sp[t] = acc / fmaxf(cnt, 1.0f);
    __syncthreads();
    if (t < OUTC) {
        float a = bf[t];
        #pragma unroll 8
        for (int k = 0; k < Fdim; k++) a += sp[k] * Wf[k * OUTC + t];
        out[g * OUTC + t] = a;
    }
}

// ---------------- launch ----------------
extern "C" void kernel_launch(void* const* d_in, const int* in_sizes, int n_in,
                              void* d_out, int out_size) {
    const float* x    = (const float*)d_in[0];
    const float* top  = (const float*)d_in[1];
    const int*   ei   = (const int*)  d_in[2];
    const int*   batch= (const int*)  d_in[3];
    const float* W0   = (const float*)d_in[4];
    const float* b0   = (const float*)d_in[5];
    const float* Wg0  = (const float*)d_in[6];
    const float* W1   = (const float*)d_in[7];
    const float* b1   = (const float*)d_in[8];
    const float* Wg1  = (const float*)d_in[9];
    const float* Wf   = (const float*)d_in[10];
    const float* bf   = (const float*)d_in[11];
    float* out = (float*)d_out;

    const int* src = ei;
    const int* dst = ei + Ee;

    cudaFuncSetAttribute(k_gemm_fused, cudaFuncAttributeMaxDynamicSharedMemorySize, DYN_SMEM);

    // CSR build + normalization + W packing
    k_init   <<<(Nn + 255) / 256, 256>>>();
    k_count  <<<(Ee + 255) / 256, 256>>>(dst);
    k_scan1  <<<NBLK, SCAN_B>>>();
    k_scan2  <<<1, 32>>>();
    k_scan3  <<<(Nn + 255) / 256, 256>>>();
    k_fill   <<<(Ee + 255) / 256, 256>>>(src, dst);
    k_wsplit2<<<96, 256>>>(W0, W1);

    int gemm_grid = (Nn + 127) / 128;

    k_gemm_fused<<<gemm_grid, 512, DYN_SMEM>>>(x, 0, b0, Wg0, top);
    k_gemm_fused<<<gemm_grid, 512, DYN_SMEM>>>(x, 1, b1, Wg1, top);

    k_poolfinal<<<Gn, 128>>>(batch, Wf, bf, out);
}

// round 10
// speedup vs baseline: 1.0620x; 1.0620x over previous
#include <cuda_runtime.h>
#include <cuda_bf16.h>
#include <cstdint>
#include <math.h>

// Problem constants
#define Nn   50000
#define Ee   800000
#define Fdim 128
#define Gn   64
#define OUTC 64
#define EXPN 3
#define TEMP_INV (1.0f/101.0f)

#define SCAN_B 1024
#define NBLK   ((Nn + SCAN_B - 1) / SCAN_B)

// A-tile smem row stride in bytes (128 bf16 = 256B, padded to 272)
#define AROW 272
#define ABYTES (128 * AROW)
#define DYN_SMEM (2 * ABYTES)

// ---------------- device scratch ----------------
__device__ float g_dinv[Nn];
__device__ int   g_degi[Nn];
__device__ int   g_off [Nn + 1];
__device__ int   g_cur [Nn];
__device__ int   g_bsum[NBLK];
__device__ int   g_csr [Ee];
__device__ float g_agg[(size_t)Nn * Fdim];
__device__ float g_h  [(size_t)Nn * Fdim];   // layer-0 output
__device__ float g_h2 [(size_t)Nn * Fdim];   // layer-1 output
// packed W fragments: [e(3)][kk(8)][ntg(16)][lane(32)] -> uint2 {b0,b1}
__device__ uint2 g_wph0[12288];
__device__ uint2 g_wpl0[12288];
__device__ uint2 g_wph1[12288];
__device__ uint2 g_wpl1[12288];

// ---------------- helpers ----------------
__device__ __forceinline__ void split2(float a, float b, uint32_t& hi, uint32_t& lo) {
    __nv_bfloat162 h = __floats2bfloat162_rn(a, b);
    float ra = a - __bfloat162float(h.x);
    float rb = b - __bfloat162float(h.y);
    __nv_bfloat162 l = __floats2bfloat162_rn(ra, rb);
    hi = *reinterpret_cast<uint32_t*>(&h);
    lo = *reinterpret_cast<uint32_t*>(&l);
}
__device__ __forceinline__ uint32_t smem_u32(const void* p) {
    uint32_t a;
    asm("{ .reg .u64 t; cvta.to.shared.u64 t, %1; cvt.u32.u64 %0, t; }" : "=r"(a) : "l"(p));
    return a;
}
__device__ __forceinline__ void ldsm4(uint32_t* r, uint32_t addr) {
    asm volatile("ldmatrix.sync.aligned.m8n8.x4.shared.b16 {%0,%1,%2,%3}, [%4];"
        : "=r"(r[0]), "=r"(r[1]), "=r"(r[2]), "=r"(r[3]) : "r"(addr));
}
__device__ __forceinline__ void mma16816(float* d, const uint32_t* a, uint2 b) {
    asm volatile("mma.sync.aligned.m16n8k16.row.col.f32.bf16.bf16.f32 "
        "{%0,%1,%2,%3}, {%4,%5,%6,%7}, {%8,%9}, {%0,%1,%2,%3};"
        : "+f"(d[0]), "+f"(d[1]), "+f"(d[2]), "+f"(d[3])
        : "r"(a[0]), "r"(a[1]), "r"(a[2]), "r"(a[3]), "r"(b.x), "r"(b.y));
}

// ---------------- CSR build ----------------
__global__ void k_init() {
    int i = blockIdx.x * blockDim.x + threadIdx.x;
    if (i < Nn) g_degi[i] = 0;
}
__global__ void k_count(const int* __restrict__ dst) {
    int e = blockIdx.x * blockDim.x + threadIdx.x;
    if (e < Ee) atomicAdd(&g_degi[dst[e]], 1);
}
__global__ void k_scan1() {      // block scan + fused rsqrt
    __shared__ int s[SCAN_B];
    int b = blockIdx.x, t = threadIdx.x;
    int i = b * SCAN_B + t;
    int v = (i < Nn) ? g_degi[i] : 0;
    if (i < Nn) g_dinv[i] = rsqrtf((float)(v + 1));   // +1 self loop
    s[t] = v;
    __syncthreads();
    for (int d = 1; d < SCAN_B; d <<= 1) {
        int add = (t >= d) ? s[t - d] : 0;
        __syncthreads();
        s[t] += add;
        __syncthreads();
    }
    if (i < Nn) g_off[i] = s[t] - v;
    if (t == SCAN_B - 1) g_bsum[b] = s[t];
}
__global__ void k_scan2() {      // parallel scan of block sums
    __shared__ int s[64];
    int t = threadIdx.x;
    int v = (t < NBLK) ? g_bsum[t] : 0;
    s[t] = v;
    __syncthreads();
    for (int d = 1; d < 64; d <<= 1) {
        int add = (t >= d) ? s[t - d] : 0;
        __syncthreads();
        s[t] += add;
        __syncthreads();
    }
    if (t < NBLK) g_bsum[t] = s[t] - v;     // exclusive
    if (t == 0) g_off[Nn] = Ee;
}
__global__ void k_scan3() {
    int i = blockIdx.x * blockDim.x + threadIdx.x;
    if (i < Nn) {
        int o = g_off[i] + g_bsum[i / SCAN_B];
        g_off[i] = o;
        g_cur[i] = o;
    }
}
__global__ void k_fill(const int* __restrict__ src, const int* __restrict__ dst) {
    int e = blockIdx.x * blockDim.x + threadIdx.x;
    if (e < Ee) {
        int pos = atomicAdd(&g_cur[dst[e]], 1);
        g_csr[pos] = src[e];
    }
}

// ---------------- W fragment packing (both layers) ----------------
__global__ void k_wsplit2(const float* __restrict__ W0, const float* __restrict__ W1) {
    int gidx = blockIdx.x * blockDim.x + threadIdx.x;
    if (gidx >= 24576) return;
    int layer = (gidx >= 12288) ? 1 : 0;
    int idx   = gidx - layer * 12288;
    int lane = idx & 31;
    int ntg  = (idx >> 5) & 15;
    int kk   = (idx >> 9) & 7;
    int e    = idx >> 12;
    int n  = ntg * 8 + (lane >> 2);
    int k0 = kk * 16 + (lane & 3) * 2;
    const float* We = (layer ? W1 : W0) + (size_t)e * Fdim * Fdim;
    uint32_t h0, l0, h1, l1;
    split2(We[(size_t)k0 * Fdim + n],       We[(size_t)(k0 + 1) * Fdim + n], h0, l0);
    split2(We[(size_t)(k0 + 8) * Fdim + n], We[(size_t)(k0 + 9) * Fdim + n], h1, l1);
    uint2* ph = layer ? g_wph1 : g_wph0;
    uint2* pl = layer ? g_wpl1 : g_wpl0;
    ph[idx] = make_uint2(h0, h1);
    pl[idx] = make_uint2(l0, l1);
}

// ---------------- gather aggregation: one warp per node ----------------
// agg[n] = dinv[n]*in[n] + sum_{s in N(n)} dinv[s]*in[s]   (final dinv[n] in GEMM)
// layer selects the input INSIDE device code (device-symbol addresses are
// invalid when taken from host).
__global__ __launch_bounds__(256)
void k_gather(const float4* __restrict__ xin, int layer) {
    int gid  = blockIdx.x * blockDim.x + threadIdx.x;
    int n    = gid >> 5;
    if (n >= Nn) return;
    int lane = gid & 31;
    const float4* P = layer ? (const float4*)g_h : xin;
    float dn = g_dinv[n];
    float4 v = P[(size_t)n * 32 + lane];
    float4 acc = make_float4(dn * v.x, dn * v.y, dn * v.z, dn * v.w);
    int e   = g_off[n];
    int end = g_off[n + 1];
    for (; e + 4 <= end; e += 4) {
        int s0 = g_csr[e],   s1 = g_csr[e+1];
        int s2 = g_csr[e+2], s3 = g_csr[e+3];
        float d0 = g_dinv[s0], d1 = g_dinv[s1], d2 = g_dinv[s2], d3 = g_dinv[s3];
        float4 v0 = P[(size_t)s0 * 32 + lane];
        float4 v1 = P[(size_t)s1 * 32 + lane];
        float4 v2 = P[(size_t)s2 * 32 + lane];
        float4 v3 = P[(size_t)s3 * 32 + lane];
        acc.x += d0*v0.x + d1*v1.x + d2*v2.x + d3*v3.x;
        acc.y += d0*v0.y + d1*v1.y + d2*v2.y + d3*v3.y;
        acc.z += d0*v0.z + d1*v1.z + d2*v2.z + d3*v3.z;
        acc.w += d0*v0.w + d1*v1.w + d2*v2.w + d3*v3.w;
    }
    for (; e < end; e++) {
        int s = g_csr[e];
        float ds = g_dinv[s];
        float4 vv = P[(size_t)s * 32 + lane];
        acc.x += ds*vv.x; acc.y += ds*vv.y; acc.z += ds*vv.z; acc.w += ds*vv.w;
    }
    ((float4*)g_agg)[(size_t)n * 32 + lane] = acc;
}

// ---------------- MoE GEMM via mma.sync bf16 split ----------------
// 512 threads, 128-node x 128-col tile. 16 warps: wm = w&3 (32 rows), wn = w>>2 (32 cols).
extern __shared__ char dynA[];   // [A_hi 34816][A_lo 34816]
__global__ __launch_bounds__(512)
void k_gemm_mma(int layer,
                const float* __restrict__ bvec, // [3,128]
                const float* __restrict__ Wg,   // [3,4]
                const float* __restrict__ top)  // [N,4]
{
    __shared__ float sgate[128][4];

    int tid  = threadIdx.x;
    int m0   = blockIdx.x * 128;

    // ---- gates ----
    if (tid < 128) {
        int n = m0 + tid;
        float l0 = 0.f, l1 = 0.f, l2 = 0.f;
        if (n < Nn) {
            float t0 = top[n*4+0], t1 = top[n*4+1], t2 = top[n*4+2], t3 = top[n*4+3];
            l0 = (t0*Wg[0] + t1*Wg[1] + t2*Wg[2]  + t3*Wg[3])  * TEMP_INV;
            l1 = (t0*Wg[4] + t1*Wg[5] + t2*Wg[6]  + t3*Wg[7])  * TEMP_INV;
            l2 = (t0*Wg[8] + t1*Wg[9] + t2*Wg[10] + t3*Wg[11]) * TEMP_INV;
        }
        float mx = fmaxf(l0, fmaxf(l1, l2));
        float e0 = __expf(l0 - mx), e1 = __expf(l1 - mx), e2 = __expf(l2 - mx);
        float inv = 1.0f / (e0 + e1 + e2);
        sgate[tid][0] = e0 * inv; sgate[tid][1] = e1 * inv; sgate[tid][2] = e2 * inv;
    }

    // ---- A tile: dinv*agg -> bf16 hi/lo in smem ----
    for (int idx = tid; idx < 8192; idx += 512) {       // 128 rows x 64 float2
        int row = idx >> 6;
        int kp  = idx & 63;
        int n   = m0 + row;
        float2 v = make_float2(0.f, 0.f);
        float  d = 0.f;
        if (n < Nn) {
            v = ((const float2*)g_agg)[(size_t)n * 64 + kp];
            d = g_dinv[n];
        }
        uint32_t hi, lo;
        split2(v.x * d, v.y * d, hi, lo);
        *reinterpret_cast<uint32_t*>(dynA + row * AROW + kp * 4)          = hi;
        *reinterpret_cast<uint32_t*>(dynA + ABYTES + row * AROW + kp * 4) = lo;
    }
    __syncthreads();

    int w    = tid >> 5;
    int lane = tid & 31;
    int wm   = w & 3;
    int wn   = w >> 2;

    uint32_t aBase  = smem_u32(dynA);
    uint32_t aAddr0 = aBase + (uint32_t)(wm * 32 + (lane & 15)) * AROW + (uint32_t)(lane >> 4) * 16;

    const uint2* wph = layer ? g_wph1 : g_wph0;
    const uint2* wpl = layer ? g_wpl1 : g_wpl0;

    float out[2][4][4];
    #pragma unroll
    for (int mt = 0; mt < 2; mt++)
        #pragma unroll
        for (int nt = 0; nt < 4; nt++)
            #pragma unroll
            for (int rr = 0; rr < 4; rr++) out[mt][nt][rr] = 0.f;

    int r0 = wm * 32 + (lane >> 2);

    for (int e = 0; e < EXPN; e++) {
        float acc[2][4][4];
        #pragma unroll
        for (int mt = 0; mt < 2; mt++)
            #pragma unroll
            for (int nt = 0; nt < 4; nt++)
                #pragma unroll
                for (int rr = 0; rr < 4; rr++) acc[mt][nt][rr] = 0.f;

        #pragma unroll
        for (int p = 0; p < 3; p++) {
            const uint2* Bp = ((p == 1) ? wpl : wph) + e * 4096 + (wn * 4) * 32 + lane;
            uint32_t aOff = aAddr0 + ((p == 2) ? ABYTES : 0u);
            #pragma unroll
            for (int kk = 0; kk < 8; kk++) {
                uint32_t a0[4], a1[4];
                ldsm4(a0, aOff + kk * 32);
                ldsm4(a1, aOff + kk * 32 + 16 * AROW);
                const uint2* Bk = Bp + kk * 512;
                #pragma unroll
                for (int nt = 0; nt < 4; nt++) {
                    uint2 b = Bk[nt * 32];
                    mma16816(acc[0][nt], a0, b);
                    mma16816(acc[1][nt], a1, b);
                }
            }
        }
        #pragma unroll
        for (int mt = 0; mt < 2; mt++) {
            float gA = sgate[r0 + mt * 16][e];
            float gB = sgate[r0 + mt * 16 + 8][e];
            #pragma unroll
            for (int nt = 0; nt < 4; nt++) {
                float2 bias = *(const float2*)(bvec + e * Fdim + wn * 32 + nt * 8 + (lane & 3) * 2);
                out[mt][nt][0] += gA * fmaxf(acc[mt][nt][0] + bias.x, 0.f);
                out[mt][nt][1] += gA * fmaxf(acc[mt][nt][1] + bias.y, 0.f);
                out[mt][nt][2] += gB * fmaxf(acc[mt][nt][2] + bias.x, 0.f);
                out[mt][nt][3] += gB * fmaxf(acc[mt][nt][3] + bias.y, 0.f);
            }
        }
    }

    float* dstbuf = layer ? g_h2 : g_h;
    #pragma unroll
    for (int mt = 0; mt < 2; mt++) {
        int ra = m0 + r0 + mt * 16;
        int rb = ra + 8;
        #pragma unroll
        for (int nt = 0; nt < 4; nt++) {
            int col = wn * 32 + nt * 8 + (lane & 3) * 2;
            if (ra < Nn)
                *(float2*)(dstbuf + (size_t)ra * Fdim + col) = make_float2(out[mt][nt][0], out[mt][nt][1]);
            if (rb < Nn)
                *(float2*)(dstbuf + (size_t)rb * Fdim + col) = make_float2(out[mt][nt][2], out[mt][nt][3]);
        }
    }
}

// ---------------- pool + final linear (one block per graph, batch sorted) ----------------
__device__ __forceinline__ int lbound(const int* __restrict__ b, int val) {
    int lo = 0, hi = Nn;
    while (lo < hi) { int mid = (lo + hi) >> 1; if (b[mid] < val) lo = mid + 1; else hi = mid; }
    return lo;
}
__global__ __launch_bounds__(128)
void k_poolfinal(const int* __restrict__ batch,
                 const float* __restrict__ Wf, const float* __restrict__ bf,
                 float* __restrict__ out) {
    __shared__ float sp[Fdim];
    int g = blockIdx.x;
    int t = threadIdx.x;
    int lo = lbound(batch, g);
    int hi = lbound(batch, g + 1);
    float acc = 0.f;
    for (int n = lo; n < hi; n++) acc += g_h2[(size_t)n * Fdim + t];
    float cnt = (float)(hi - lo);
    sp[t] = acc / fmaxf(cnt, 1.0f);
    __syncthreads();
    if (t < OUTC) {
        float a = bf[t];
        #pragma unroll 8
        for (int k = 0; k < Fdim; k++) a += sp[k] * Wf[k * OUTC + t];
        out[g * OUTC + t] = a;
    }
}

// ---------------- launch ----------------
extern "C" void kernel_launch(void* const* d_in, const int* in_sizes, int n_in,
                              void* d_out, int out_size) {
    const float* x    = (const float*)d_in[0];
    const float* top  = (const float*)d_in[1];
    const int*   ei   = (const int*)  d_in[2];
    const int*   batch= (const int*)  d_in[3];
    const float* W0   = (const float*)d_in[4];
    const float* b0   = (const float*)d_in[5];
    const float* Wg0  = (const float*)d_in[6];
    const float* W1   = (const float*)d_in[7];
    const float* b1   = (const float*)d_in[8];
    const float* Wg1  = (const float*)d_in[9];
    const float* Wf   = (const float*)d_in[10];
    const float* bf   = (const float*)d_in[11];
    float* out = (float*)d_out;

    const int* src = ei;
    const int* dst = ei + Ee;

    cudaFuncSetAttribute(k_gemm_mma, cudaFuncAttributeMaxDynamicSharedMemorySize, DYN_SMEM);

    // CSR build + normalization + W packing
    k_init   <<<(Nn + 255) / 256, 256>>>();
    k_count  <<<(Ee + 255) / 256, 256>>>(dst);
    k_scan1  <<<NBLK, SCAN_B>>>();
    k_scan2  <<<1, 64>>>();
    k_scan3  <<<(Nn + 255) / 256, 256>>>();
    k_fill   <<<(Ee + 255) / 256, 256>>>(src, dst);
    k_wsplit2<<<96, 256>>>(W0, W1);

    int gw = (Nn * 32 + 255) / 256;
    int gg = (Nn + 127) / 128;

    // layer 0
    k_gather  <<<gw, 256>>>((const float4*)x, 0);
    k_gemm_mma<<<gg, 512, DYN_SMEM>>>(0, b0, Wg0, top);

    // layer 1
    k_gather  <<<gw, 256>>>((const float4*)x, 1);
    k_gemm_mma<<<gg, 512, DYN_SMEM>>>(1, b1, Wg1, top);

    // pool + final
    k_poolfinal<<<Gn, 128>>>(batch, Wf, bf, out);
}

// round 12
// speedup vs baseline: 1.1707x; 1.1024x over previous
#include <cuda_runtime.h>
#include <cuda_bf16.h>
#include <cstdint>
#include <math.h>

// Problem constants
#define Nn   50000
#define Ee   800000
#define Fdim 128
#define Gn   64
#define OUTC 64
#define EXPN 3
#define TEMP_INV (1.0f/101.0f)

#define SCAN_B 1024
#define NBLK   ((Nn + SCAN_B - 1) / SCAN_B)

// A-tile smem row stride in bytes (128 bf16 = 256B, padded to 272)
#define AROW 272
#define ABYTES (128 * AROW)
#define DYN_SMEM (2 * ABYTES)     // 69632; also reused as 128x128 f32 staging (65536)

// ---------------- device scratch ----------------
__device__ float g_dinv[Nn];
__device__ int   g_degi[Nn];
__device__ int   g_off [Nn + 1];
__device__ int   g_cur [Nn];
__device__ int   g_bsum[NBLK];
__device__ int   g_csr [Ee];
__device__ float g_agg[(size_t)Nn * Fdim];
__device__ float g_h  [(size_t)Nn * Fdim];   // layer-0 output, PRE-SCALED by dinv
__device__ float g_pool[Gn * Fdim];
// packed W fragments: [e(3)][kk(8)][ntg(16)][lane(32)] -> uint2 {b0,b1}
__device__ uint2 g_wph0[12288];
__device__ uint2 g_wpl0[12288];
__device__ uint2 g_wph1[12288];
__device__ uint2 g_wpl1[12288];

// ---------------- helpers ----------------
__device__ __forceinline__ void split2(float a, float b, uint32_t& hi, uint32_t& lo) {
    __nv_bfloat162 h = __floats2bfloat162_rn(a, b);
    float ra = a - __bfloat162float(h.x);
    float rb = b - __bfloat162float(h.y);
    __nv_bfloat162 l = __floats2bfloat162_rn(ra, rb);
    hi = *reinterpret_cast<uint32_t*>(&h);
    lo = *reinterpret_cast<uint32_t*>(&l);
}
__device__ __forceinline__ uint32_t smem_u32(const void* p) {
    uint32_t a;
    asm("{ .reg .u64 t; cvta.to.shared.u64 t, %1; cvt.u32.u64 %0, t; }" : "=r"(a) : "l"(p));
    return a;
}
__device__ __forceinline__ void ldsm4(uint32_t* r, uint32_t addr) {
    asm volatile("ldmatrix.sync.aligned.m8n8.x4.shared.b16 {%0,%1,%2,%3}, [%4];"
        : "=r"(r[0]), "=r"(r[1]), "=r"(r[2]), "=r"(r[3]) : "r"(addr));
}
__device__ __forceinline__ void mma16816(float* d, const uint32_t* a, uint2 b) {
    asm volatile("mma.sync.aligned.m16n8k16.row.col.f32.bf16.bf16.f32 "
        "{%0,%1,%2,%3}, {%4,%5,%6,%7}, {%8,%9}, {%0,%1,%2,%3};"
        : "+f"(d[0]), "+f"(d[1]), "+f"(d[2]), "+f"(d[3])
        : "r"(a[0]), "r"(a[1]), "r"(a[2]), "r"(a[3]), "r"(b.x), "r"(b.y));
}

// ---------------- init + W packing (fused) ----------------
__global__ void k_initw(const float* __restrict__ W0, const float* __restrict__ W1) {
    int gidx = blockIdx.x * blockDim.x + threadIdx.x;
    if (gidx < Nn) g_degi[gidx] = 0;
    if (gidx < Gn * Fdim) g_pool[gidx] = 0.f;
    if (gidx < 24576) {
        int layer = (gidx >= 12288) ? 1 : 0;
        int idx   = gidx - layer * 12288;
        int lane = idx & 31;
        int ntg  = (idx >> 5) & 15;
        int kk   = (idx >> 9) & 7;
        int e    = idx >> 12;
        int n  = ntg * 8 + (lane >> 2);
        int k0 = kk * 16 + (lane & 3) * 2;
        const float* We = (layer ? W1 : W0) + (size_t)e * Fdim * Fdim;
        uint32_t h0, l0, h1, l1;
        split2(We[(size_t)k0 * Fdim + n],       We[(size_t)(k0 + 1) * Fdim + n], h0, l0);
        split2(We[(size_t)(k0 + 8) * Fdim + n], We[(size_t)(k0 + 9) * Fdim + n], h1, l1);
        uint2* ph = layer ? g_wph1 : g_wph0;
        uint2* pl = layer ? g_wpl1 : g_wpl0;
        ph[idx] = make_uint2(h0, h1);
        pl[idx] = make_uint2(l0, l1);
    }
}

// ---------------- CSR build ----------------
__global__ void k_count(const int* __restrict__ dst) {
    int e = blockIdx.x * blockDim.x + threadIdx.x;
    if (e < Ee) atomicAdd(&g_degi[dst[e]], 1);
}
__global__ void k_scan1() {      // block scan + fused rsqrt
    __shared__ int s[SCAN_B];
    int b = blockIdx.x, t = threadIdx.x;
    int i = b * SCAN_B + t;
    int v = (i < Nn) ? g_degi[i] : 0;
    if (i < Nn) g_dinv[i] = rsqrtf((float)(v + 1));   // +1 self loop
    s[t] = v;
    __syncthreads();
    for (int d = 1; d < SCAN_B; d <<= 1) {
        int add = (t >= d) ? s[t - d] : 0;
        __syncthreads();
        s[t] += add;
        __syncthreads();
    }
    if (i < Nn) g_off[i] = s[t] - v;
    if (t == SCAN_B - 1) g_bsum[b] = s[t];
}
// scan of block sums done redundantly per block (NBLK=49 fits one warp sweep)
__global__ void k_scan3() {
    __shared__ int s[64];
    int t = threadIdx.x;
    if (t < 64) s[t] = (t < NBLK) ? g_bsum[t] : 0;
    __syncthreads();
    for (int d = 1; d < 64; d <<= 1) {
        int add = (t < 64 && t >= d) ? s[t - d] : 0;
        __syncthreads();
        if (t < 64) s[t] += add;
        __syncthreads();
    }
    int i = blockIdx.x * blockDim.x + t;
    if (i < Nn) {
        int blk = i / SCAN_B;
        int ex  = (blk == 0) ? 0 : s[blk - 1];   // exclusive prefix
        int o = g_off[i] + ex;
        g_off[i] = o;
        g_cur[i] = o;
    }
    if (i == 0) g_off[Nn] = Ee;
}
__global__ void k_fill(const int* __restrict__ src, const int* __restrict__ dst) {
    int e = blockIdx.x * blockDim.x + threadIdx.x;
    if (e < Ee) {
        int pos = atomicAdd(&g_cur[dst[e]], 1);
        g_csr[pos] = src[e];
    }
}

// ---------------- gather aggregation: one warp per node ----------------
// layer 0: in = x (unscaled)       -> acc = dn*x[n] + sum ds*x[s]
// layer 1: in = g_h (= dinv*h)     -> acc = p[n] + sum p[s]      (no dinv loads)
__global__ __launch_bounds__(256)
void k_gather(const float4* __restrict__ xin, int layer) {
    int gid  = blockIdx.x * blockDim.x + threadIdx.x;
    int n    = gid >> 5;
    if (n >= Nn) return;
    int lane = gid & 31;
    int e   = g_off[n];
    int end = g_off[n + 1];
    float4 acc;
    if (layer == 0) {
        const float4* P = xin;
        float dn = g_dinv[n];
        float4 v = P[(size_t)n * 32 + lane];
        acc = make_float4(dn * v.x, dn * v.y, dn * v.z, dn * v.w);
        for (; e + 4 <= end; e += 4) {
            int s0 = g_csr[e],   s1 = g_csr[e+1];
            int s2 = g_csr[e+2], s3 = g_csr[e+3];
            float d0 = g_dinv[s0], d1 = g_dinv[s1], d2 = g_dinv[s2], d3 = g_dinv[s3];
            float4 v0 = P[(size_t)s0 * 32 + lane];
            float4 v1 = P[(size_t)s1 * 32 + lane];
            float4 v2 = P[(size_t)s2 * 32 + lane];
            float4 v3 = P[(size_t)s3 * 32 + lane];
            acc.x += d0*v0.x + d1*v1.x + d2*v2.x + d3*v3.x;
            acc.y += d0*v0.y + d1*v1.y + d2*v2.y + d3*v3.y;
            acc.z += d0*v0.z + d1*v1.z + d2*v2.z + d3*v3.z;
            acc.w += d0*v0.w + d1*v1.w + d2*v2.w + d3*v3.w;
        }
        for (; e < end; e++) {
            int s = g_csr[e];
            float ds = g_dinv[s];
            float4 vv = P[(size_t)s * 32 + lane];
            acc.x += ds*vv.x; acc.y += ds*vv.y; acc.z += ds*vv.z; acc.w += ds*vv.w;
        }
    } else {
        const float4* P = (const float4*)g_h;
        acc = P[(size_t)n * 32 + lane];
        for (; e + 4 <= end; e += 4) {
            int s0 = g_csr[e],   s1 = g_csr[e+1];
            int s2 = g_csr[e+2], s3 = g_csr[e+3];
            float4 v0 = P[(size_t)s0 * 32 + lane];
            float4 v1 = P[(size_t)s1 * 32 + lane];
            float4 v2 = P[(size_t)s2 * 32 + lane];
            float4 v3 = P[(size_t)s3 * 32 + lane];
            acc.x += v0.x + v1.x + v2.x + v3.x;
            acc.y += v0.y + v1.y + v2.y + v3.y;
            acc.z += v0.z + v1.z + v2.z + v3.z;
            acc.w += v0.w + v1.w + v2.w + v3.w;
        }
        for (; e < end; e++) {
            int s = g_csr[e];
            float4 vv = P[(size_t)s * 32 + lane];
            acc.x += vv.x; acc.y += vv.y; acc.z += vv.z; acc.w += vv.w;
        }
    }
    ((float4*)g_agg)[(size_t)n * 32 + lane] = acc;
}

// ---------------- MoE GEMM via mma.sync bf16 split ----------------
// 512 threads, 128-node x 128-col tile. 16 warps: wm = w&3 (32 rows), wn = w>>2 (32 cols).
// layer 0: store dinv*result to g_h.  layer 1: pool directly (smem staging + atomics).
extern __shared__ char dynA[];
__global__ __launch_bounds__(512)
void k_gemm_mma(int layer,
                const float* __restrict__ bvec, // [3,128]
                const float* __restrict__ Wg,   // [3,4]
                const float* __restrict__ top,  // [N,4]
                const int* __restrict__ batch)  // [N]
{
    __shared__ float sgate[128][4];

    int tid  = threadIdx.x;
    int m0   = blockIdx.x * 128;

    // ---- gates ----
    if (tid < 128) {
        int n = m0 + tid;
        float l0 = 0.f, l1 = 0.f, l2 = 0.f;
        if (n < Nn) {
            float t0 = top[n*4+0], t1 = top[n*4+1], t2 = top[n*4+2], t3 = top[n*4+3];
            l0 = (t0*Wg[0] + t1*Wg[1] + t2*Wg[2]  + t3*Wg[3])  * TEMP_INV;
            l1 = (t0*Wg[4] + t1*Wg[5] + t2*Wg[6]  + t3*Wg[7])  * TEMP_INV;
            l2 = (t0*Wg[8] + t1*Wg[9] + t2*Wg[10] + t3*Wg[11]) * TEMP_INV;
        }
        float mx = fmaxf(l0, fmaxf(l1, l2));
        float e0 = __expf(l0 - mx), e1 = __expf(l1 - mx), e2 = __expf(l2 - mx);
        float inv = 1.0f / (e0 + e1 + e2);
        sgate[tid][0] = e0 * inv; sgate[tid][1] = e1 * inv; sgate[tid][2] = e2 * inv;
    }

    // ---- A tile: dinv*agg -> bf16 hi/lo in smem ----
    for (int idx = tid; idx < 8192; idx += 512) {       // 128 rows x 64 float2
        int row = idx >> 6;
        int kp  = idx & 63;
        int n   = m0 + row;
        float2 v = make_float2(0.f, 0.f);
        float  d = 0.f;
        if (n < Nn) {
            v = ((const float2*)g_agg)[(size_t)n * 64 + kp];
            d = g_dinv[n];
        }
        uint32_t hi, lo;
        split2(v.x * d, v.y * d, hi, lo);
        *reinterpret_cast<uint32_t*>(dynA + row * AROW + kp * 4)          = hi;
        *reinterpret_cast<uint32_t*>(dynA + ABYTES + row * AROW + kp * 4) = lo;
    }
    __syncthreads();

    int w    = tid >> 5;
    int lane = tid & 31;
    int wm   = w & 3;
    int wn   = w >> 2;

    uint32_t aBase  = smem_u32(dynA);
    uint32_t aAddr0 = aBase + (uint32_t)(wm * 32 + (lane & 15)) * AROW + (uint32_t)(lane >> 4) * 16;

    const uint2* wph = layer ? g_wph1 : g_wph0;
    const uint2* wpl = layer ? g_wpl1 : g_wpl0;

    float out[2][4][4];
    #pragma unroll
    for (int mt = 0; mt < 2; mt++)
        #pragma unroll
        for (int nt = 0; nt < 4; nt++)
            #pragma unroll
            for (int rr = 0; rr < 4; rr++) out[mt][nt][rr] = 0.f;

    int r0 = wm * 32 + (lane >> 2);

    for (int e = 0; e < EXPN; e++) {
        float acc[2][4][4];
        #pragma unroll
        for (int mt = 0; mt < 2; mt++)
            #pragma unroll
            for (int nt = 0; nt < 4; nt++)
                #pragma unroll
                for (int rr = 0; rr < 4; rr++) acc[mt][nt][rr] = 0.f;

        #pragma unroll
        for (int p = 0; p < 3; p++) {
            const uint2* Bp = ((p == 1) ? wpl : wph) + e * 4096 + (wn * 4) * 32 + lane;
            uint32_t aOff = aAddr0 + ((p == 2) ? ABYTES : 0u);
            #pragma unroll
            for (int kk = 0; kk < 8; kk++) {
                uint32_t a0[4], a1[4];
                ldsm4(a0, aOff + kk * 32);
                ldsm4(a1, aOff + kk * 32 + 16 * AROW);
                const uint2* Bk = Bp + kk * 512;
                #pragma unroll
                for (int nt = 0; nt < 4; nt++) {
                    uint2 b = Bk[nt * 32];
                    mma16816(acc[0][nt], a0, b);
                    mma16816(acc[1][nt], a1, b);
                }
            }
        }
        #pragma unroll
        for (int mt = 0; mt < 2; mt++) {
            float gA = sgate[r0 + mt * 16][e];
            float gB = sgate[r0 + mt * 16 + 8][e];
            #pragma unroll
            for (int nt = 0; nt < 4; nt++) {
                float2 bias = *(const float2*)(bvec + e * Fdim + wn * 32 + nt * 8 + (lane & 3) * 2);
                out[mt][nt][0] += gA * fmaxf(acc[mt][nt][0] + bias.x, 0.f);
                out[mt][nt][1] += gA * fmaxf(acc[mt][nt][1] + bias.y, 0.f);
                out[mt][nt][2] += gB * fmaxf(acc[mt][nt][2] + bias.x, 0.f);
                out[mt][nt][3] += gB * fmaxf(acc[mt][nt][3] + bias.y, 0.f);
            }
        }
    }

    if (layer == 0) {
        // store p = dinv * result (pre-scaled for next layer's gather)
        #pragma unroll
        for (int mt = 0; mt < 2; mt++) {
            int ra = m0 + r0 + mt * 16;
            int rb = ra + 8;
            #pragma unroll
            for (int nt = 0; nt < 4; nt++) {
                int col = wn * 32 + nt * 8 + (lane & 3) * 2;
                if (ra < Nn) {
                    float da = g_dinv[ra];
                    *(float2*)(g_h + (size_t)ra * Fdim + col) =
                        make_float2(da * out[mt][nt][0], da * out[mt][nt][1]);
                }
                if (rb < Nn) {
                    float db = g_dinv[rb];
                    *(float2*)(g_h + (size_t)rb * Fdim + col) =
                        make_float2(db * out[mt][nt][2], db * out[mt][nt][3]);
                }
            }
        }
    } else {
        // pool directly: stage tile in smem (reuse dynA), segmented sums -> atomics
        float* sT = (float*)dynA;               // 128x128 f32 = 64KB <= 69.6KB
        __syncthreads();                         // all A-tile reads done
        #pragma unroll
        for (int mt = 0; mt < 2; mt++) {
            int ra = r0 + mt * 16;
            #pragma unroll
            for (int nt = 0; nt < 4; nt++) {
                int col = wn * 32 + nt * 8 + (lane & 3) * 2;
                sT[ra * 128 + col]           = out[mt][nt][0];
                sT[ra * 128 + col + 1]       = out[mt][nt][1];
                sT[(ra + 8) * 128 + col]     = out[mt][nt][2];
                sT[(ra + 8) * 128 + col + 1] = out[mt][nt][3];
            }
        }
        __syncthreads();
        int c = tid & 127;
        int q = tid >> 7;                        // 0..3, 32 rows each
        int rbeg = q * 32;
        float acc = 0.f;
        int curg = -1;
        for (int r = rbeg; r < rbeg + 32; r++) {
            int n = m0 + r;
            if (n >= Nn) break;
            int g = batch[n];
            if (g != curg) {
                if (curg >= 0) atomicAdd(&g_pool[curg * Fdim + c], acc);
                acc = 0.f; curg = g;
            }
            acc += sT[r * 128 + c];
        }
        if (curg >= 0) atomicAdd(&g_pool[curg * Fdim + c], acc);
    }
}

// ---------------- final: mean + linear (batch sorted; counts via binary search) ----------------
__device__ __forceinline__ int lbound(const int* __restrict__ b, int val) {
    int lo = 0, hi = Nn;
    while (lo < hi) { int mid = (lo + hi) >> 1; if (b[mid] < val) lo = mid + 1; else hi = mid; }
    return lo;
}
__global__ __launch_bounds__(128)
void k_final(const int* __restrict__ batch,
             const float* __restrict__ Wf, const float* __restrict__ bf,
             float* __restrict__ out) {
    __shared__ float sp[Fdim];
    int g = blockIdx.x;
    int t = threadIdx.x;
    int lo = lbound(batch, g);
    int hi = lbound(batch, g + 1);
    float cnt = (float)(hi - lo);
    sp[t] = g_pool[g * Fdim + t] / fmaxf(cnt, 1.0f);
    __syncthreads();
    if (t < OUTC) {
        float a = bf[t];
        #pragma unroll 8
        for (int k = 0; k < Fdim; k++) a += sp[k] * Wf[k * OUTC + t];
        out[g * OUTC + t] = a;
    }
}

// ---------------- launch ----------------
extern "C" void kernel_launch(void* const* d_in, const int* in_sizes, int n_in,
                              void* d_out, int out_size) {
    const float* x    = (const float*)d_in[0];
    const float* top  = (const float*)d_in[1];
    const int*   ei   = (const int*)  d_in[2];
    const int*   batch= (const int*)  d_in[3];
    const float* W0   = (const float*)d_in[4];
    const float* b0   = (const float*)d_in[5];
    const float* Wg0  = (const float*)d_in[6];
    const float* W1   = (const float*)d_in[7];
    const float* b1   = (const float*)d_in[8];
    const float* Wg1  = (const float*)d_in[9];
    const float* Wf   = (const float*)d_in[10];
    const float* bf   = (const float*)d_in[11];
    float* out = (float*)d_out;

    const int* src = ei;
    const int* dst = ei + Ee;

    cudaFuncSetAttribute(k_gemm_mma, cudaFuncAttributeMaxDynamicSharedMemorySize, DYN_SMEM);

    // init + W packing, CSR build
    k_initw <<<(Nn + 255) / 256, 256>>>(W0, W1);
    k_count <<<(Ee + 255) / 256, 256>>>(dst);
    k_scan1 <<<NBLK, SCAN_B>>>();
    k_scan3 <<<(Nn + 255) / 256, 256>>>();
    k_fill  <<<(Ee + 255) / 256, 256>>>(src, dst);

    int gw = (Nn * 32 + 255) / 256;
    int gg = (Nn + 127) / 128;

    // layer 0
    k_gather  <<<gw, 256>>>((const float4*)x, 0);
    k_gemm_mma<<<gg, 512, DYN_SMEM>>>(0, b0, Wg0, top, batch);

    // layer 1 (gather reads pre-scaled g_h; gemm pools directly)
    k_gather  <<<gw, 256>>>((const float4*)x, 1);
    k_gemm_mma<<<gg, 512, DYN_SMEM>>>(1, b1, Wg1, top, batch);

    // final
    k_final<<<Gn, 128>>>(batch, Wf, bf, out);
}

// round 13
// speedup vs baseline: 1.2479x; 1.0659x over previous
#include <cuda_runtime.h>
#include <cuda_bf16.h>
#include <cuda_fp16.h>
#include <cstdint>
#include <math.h>

// Problem constants
#define Nn   50000
#define Ee   800000
#define Fdim 128
#define Gn   64
#define OUTC 64
#define EXPN 3
#define TEMP_INV (1.0f/101.0f)

#define SCAN_B 1024
#define NBLK   ((Nn + SCAN_B - 1) / SCAN_B)

// A-tile smem row stride in bytes (128 bf16 = 256B, padded to 272)
#define AROW 272
#define ABYTES (128 * AROW)
#define DYN_SMEM (2 * ABYTES)     // 69632; also reused as 128x128 f32 staging (65536)

// ---------------- device scratch ----------------
__device__ float g_dinv[Nn];
__device__ int   g_degi[Nn];
__device__ int   g_off [Nn + 1];
__device__ int   g_cur [Nn];
__device__ int   g_bsum[NBLK];
__device__ int   g_csr [Ee];
__device__ float g_agg[(size_t)Nn * Fdim];
__device__ uint2 g_ph [(size_t)Nn * 32];     // fp16 payload p = dinv*h (4 halves per uint2)
__device__ float g_pool[Gn * Fdim];
// packed W fragments: [e(3)][kk(8)][ntg(16)][lane(32)] -> uint2 {b0,b1}
__device__ uint2 g_wph0[12288];
__device__ uint2 g_wpl0[12288];
__device__ uint2 g_wph1[12288];
__device__ uint2 g_wpl1[12288];

// ---------------- helpers ----------------
__device__ __forceinline__ void split2(float a, float b, uint32_t& hi, uint32_t& lo) {
    __nv_bfloat162 h = __floats2bfloat162_rn(a, b);
    float ra = a - __bfloat162float(h.x);
    float rb = b - __bfloat162float(h.y);
    __nv_bfloat162 l = __floats2bfloat162_rn(ra, rb);
    hi = *reinterpret_cast<uint32_t*>(&h);
    lo = *reinterpret_cast<uint32_t*>(&l);
}
__device__ __forceinline__ uint32_t smem_u32(const void* p) {
    uint32_t a;
    asm("{ .reg .u64 t; cvta.to.shared.u64 t, %1; cvt.u32.u64 %0, t; }" : "=r"(a) : "l"(p));
    return a;
}
__device__ __forceinline__ void ldsm4(uint32_t* r, uint32_t addr) {
    asm volatile("ldmatrix.sync.aligned.m8n8.x4.shared.b16 {%0,%1,%2,%3}, [%4];"
        : "=r"(r[0]), "=r"(r[1]), "=r"(r[2]), "=r"(r[3]) : "r"(addr));
}
__device__ __forceinline__ void mma16816(float* d, const uint32_t* a, uint2 b) {
    asm volatile("mma.sync.aligned.m16n8k16.row.col.f32.bf16.bf16.f32 "
        "{%0,%1,%2,%3}, {%4,%5,%6,%7}, {%8,%9}, {%0,%1,%2,%3};"
        : "+f"(d[0]), "+f"(d[1]), "+f"(d[2]), "+f"(d[3])
        : "r"(a[0]), "r"(a[1]), "r"(a[2]), "r"(a[3]), "r"(b.x), "r"(b.y));
}
__device__ __forceinline__ float4 h4_to_f4(uint2 u) {
    half2 a = *reinterpret_cast<half2*>(&u.x);
    half2 b = *reinterpret_cast<half2*>(&u.y);
    float2 fa = __half22float2(a);
    float2 fb = __half22float2(b);
    return make_float4(fa.x, fa.y, fb.x, fb.y);
}

// ---------------- init + W packing (fused) ----------------
__global__ void k_initw(const float* __restrict__ W0, const float* __restrict__ W1) {
    int gidx = blockIdx.x * blockDim.x + threadIdx.x;
    if (gidx < Nn) g_degi[gidx] = 0;
    if (gidx < Gn * Fdim) g_pool[gidx] = 0.f;
    if (gidx < 24576) {
        int layer = (gidx >= 12288) ? 1 : 0;
        int idx   = gidx - layer * 12288;
        int lane = idx & 31;
        int ntg  = (idx >> 5) & 15;
        int kk   = (idx >> 9) & 7;
        int e    = idx >> 12;
        int n  = ntg * 8 + (lane >> 2);
        int k0 = kk * 16 + (lane & 3) * 2;
        const float* We = (layer ? W1 : W0) + (size_t)e * Fdim * Fdim;
        uint32_t h0, l0, h1, l1;
        split2(We[(size_t)k0 * Fdim + n],       We[(size_t)(k0 + 1) * Fdim + n], h0, l0);
        split2(We[(size_t)(k0 + 8) * Fdim + n], We[(size_t)(k0 + 9) * Fdim + n], h1, l1);
        uint2* ph = layer ? g_wph1 : g_wph0;
        uint2* pl = layer ? g_wpl1 : g_wpl0;
        ph[idx] = make_uint2(h0, h1);
        pl[idx] = make_uint2(l0, l1);
    }
}

// ---------------- CSR build ----------------
__global__ void k_count(const int* __restrict__ dst) {
    int e = blockIdx.x * blockDim.x + threadIdx.x;
    if (e < Ee) atomicAdd(&g_degi[dst[e]], 1);
}
__global__ void k_scan1() {      // block scan + fused rsqrt
    __shared__ int s[SCAN_B];
    int b = blockIdx.x, t = threadIdx.x;
    int i = b * SCAN_B + t;
    int v = (i < Nn) ? g_degi[i] : 0;
    if (i < Nn) g_dinv[i] = rsqrtf((float)(v + 1));   // +1 self loop
    s[t] = v;
    __syncthreads();
    for (int d = 1; d < SCAN_B; d <<= 1) {
        int add = (t >= d) ? s[t - d] : 0;
        __syncthreads();
        s[t] += add;
        __syncthreads();
    }
    if (i < Nn) g_off[i] = s[t] - v;
    if (t == SCAN_B - 1) g_bsum[b] = s[t];
}
// scan of block sums done redundantly per block (NBLK=49 fits one warp sweep)
__global__ void k_scan3() {
    __shared__ int s[64];
    int t = threadIdx.x;
    if (t < 64) s[t] = (t < NBLK) ? g_bsum[t] : 0;
    __syncthreads();
    for (int d = 1; d < 64; d <<= 1) {
        int add = (t < 64 && t >= d) ? s[t - d] : 0;
        __syncthreads();
        if (t < 64) s[t] += add;
        __syncthreads();
    }
    int i = blockIdx.x * blockDim.x + t;
    if (i < Nn) {
        int blk = i / SCAN_B;
        int ex  = (blk == 0) ? 0 : s[blk - 1];   // exclusive prefix
        int o = g_off[i] + ex;
        g_off[i] = o;
        g_cur[i] = o;
    }
    if (i == 0) g_off[Nn] = Ee;
}
// fill CSR (edge threads) + prescale x into fp16 payload (node threads), one launch
__global__ void k_fill_prep(const int* __restrict__ src, const int* __restrict__ dst,
                            const float4* __restrict__ x) {
    int i = blockIdx.x * blockDim.x + threadIdx.x;
    if (i < Ee) {
        int pos = atomicAdd(&g_cur[dst[i]], 1);
        g_csr[pos] = src[i];
    }
    if (i < Nn * 32) {
        int n = i >> 5;
        float d = g_dinv[n];
        float4 v = x[i];
        half2 h0 = __floats2half2_rn(v.x * d, v.y * d);
        half2 h1 = __floats2half2_rn(v.z * d, v.w * d);
        uint2 u;
        u.x = *reinterpret_cast<uint32_t*>(&h0);
        u.y = *reinterpret_cast<uint32_t*>(&h1);
        g_ph[i] = u;
    }
}

// ---------------- gather aggregation: one warp per node, pure fp16 row sum ----------------
// agg[n] = p[n] + sum_{s in N(n)} p[s]   (p = dinv*h fp16; final dinv[n] in GEMM)
__global__ __launch_bounds__(256)
void k_gather() {
    int gid  = blockIdx.x * blockDim.x + threadIdx.x;
    int n    = gid >> 5;
    if (n >= Nn) return;
    int lane = gid & 31;
    const uint2* PH = g_ph;
    float4 acc = h4_to_f4(PH[(size_t)n * 32 + lane]);
    int e   = g_off[n];
    int end = g_off[n + 1];
    for (; e + 4 <= end; e += 4) {
        int s0 = g_csr[e],   s1 = g_csr[e+1];
        int s2 = g_csr[e+2], s3 = g_csr[e+3];
        float4 v0 = h4_to_f4(PH[(size_t)s0 * 32 + lane]);
        float4 v1 = h4_to_f4(PH[(size_t)s1 * 32 + lane]);
        float4 v2 = h4_to_f4(PH[(size_t)s2 * 32 + lane]);
        float4 v3 = h4_to_f4(PH[(size_t)s3 * 32 + lane]);
        acc.x += v0.x + v1.x + v2.x + v3.x;
        acc.y += v0.y + v1.y + v2.y + v3.y;
        acc.z += v0.z + v1.z + v2.z + v3.z;
        acc.w += v0.w + v1.w + v2.w + v3.w;
    }
    for (; e < end; e++) {
        int s = g_csr[e];
        float4 vv = h4_to_f4(PH[(size_t)s * 32 + lane]);
        acc.x += vv.x; acc.y += vv.y; acc.z += vv.z; acc.w += vv.w;
    }
    ((float4*)g_agg)[(size_t)n * 32 + lane] = acc;
}

// ---------------- MoE GEMM via mma.sync bf16 split ----------------
// 512 threads, 128-node x 128-col tile. 16 warps: wm = w&3 (32 rows), wn = w>>2 (32 cols).
// layer 0: store fp16 payload p = dinv*result.  layer 1: pool directly.
extern __shared__ char dynA[];
__global__ __launch_bounds__(512)
void k_gemm_mma(int layer,
                const float* __restrict__ bvec, // [3,128]
                const float* __restrict__ Wg,   // [3,4]
                const float* __restrict__ top,  // [N,4]
                const int* __restrict__ batch)  // [N]
{
    __shared__ float sgate[128][4];

    int tid  = threadIdx.x;
    int m0   = blockIdx.x * 128;

    // ---- gates ----
    if (tid < 128) {
        int n = m0 + tid;
        float l0 = 0.f, l1 = 0.f, l2 = 0.f;
        if (n < Nn) {
            float t0 = top[n*4+0], t1 = top[n*4+1], t2 = top[n*4+2], t3 = top[n*4+3];
            l0 = (t0*Wg[0] + t1*Wg[1] + t2*Wg[2]  + t3*Wg[3])  * TEMP_INV;
            l1 = (t0*Wg[4] + t1*Wg[5] + t2*Wg[6]  + t3*Wg[7])  * TEMP_INV;
            l2 = (t0*Wg[8] + t1*Wg[9] + t2*Wg[10] + t3*Wg[11]) * TEMP_INV;
        }
        float mx = fmaxf(l0, fmaxf(l1, l2));
        float e0 = __expf(l0 - mx), e1 = __expf(l1 - mx), e2 = __expf(l2 - mx);
        float inv = 1.0f / (e0 + e1 + e2);
        sgate[tid][0] = e0 * inv; sgate[tid][1] = e1 * inv; sgate[tid][2] = e2 * inv;
    }

    // ---- A tile: dinv*agg -> bf16 hi/lo in smem ----
    for (int idx = tid; idx < 8192; idx += 512) {       // 128 rows x 64 float2
        int row = idx >> 6;
        int kp  = idx & 63;
        int n   = m0 + row;
        float2 v = make_float2(0.f, 0.f);
        float  d = 0.f;
        if (n < Nn) {
            v = ((const float2*)g_agg)[(size_t)n * 64 + kp];
            d = g_dinv[n];
        }
        uint32_t hi, lo;
        split2(v.x * d, v.y * d, hi, lo);
        *reinterpret_cast<uint32_t*>(dynA + row * AROW + kp * 4)          = hi;
        *reinterpret_cast<uint32_t*>(dynA + ABYTES + row * AROW + kp * 4) = lo;
    }
    __syncthreads();

    int w    = tid >> 5;
    int lane = tid & 31;
    int wm   = w & 3;
    int wn   = w >> 2;

    uint32_t aBase  = smem_u32(dynA);
    uint32_t aAddr0 = aBase + (uint32_t)(wm * 32 + (lane & 15)) * AROW + (uint32_t)(lane >> 4) * 16;

    const uint2* wph = layer ? g_wph1 : g_wph0;
    const uint2* wpl = layer ? g_wpl1 : g_wpl0;

    float out[2][4][4];
    #pragma unroll
    for (int mt = 0; mt < 2; mt++)
        #pragma unroll
        for (int nt = 0; nt < 4; nt++)
            #pragma unroll
            for (int rr = 0; rr < 4; rr++) out[mt][nt][rr] = 0.f;

    int r0 = wm * 32 + (lane >> 2);

    for (int e = 0; e < EXPN; e++) {
        float acc[2][4][4];
        #pragma unroll
        for (int mt = 0; mt < 2; mt++)
            #pragma unroll
            for (int nt = 0; nt < 4; nt++)
                #pragma unroll
                for (int rr = 0; rr < 4; rr++) acc[mt][nt][rr] = 0.f;

        #pragma unroll
        for (int p = 0; p < 3; p++) {
            const uint2* Bp = ((p == 1) ? wpl : wph) + e * 4096 + (wn * 4) * 32 + lane;
            uint32_t aOff = aAddr0 + ((p == 2) ? ABYTES : 0u);
            #pragma unroll
            for (int kk = 0; kk < 8; kk++) {
                uint32_t a0[4], a1[4];
                ldsm4(a0, aOff + kk * 32);
                ldsm4(a1, aOff + kk * 32 + 16 * AROW);
                const uint2* Bk = Bp + kk * 512;
                #pragma unroll
                for (int nt = 0; nt < 4; nt++) {
                    uint2 b = Bk[nt * 32];
                    mma16816(acc[0][nt], a0, b);
                    mma16816(acc[1][nt], a1, b);
                }
            }
        }
        #pragma unroll
        for (int mt = 0; mt < 2; mt++) {
            float gA = sgate[r0 + mt * 16][e];
            float gB = sgate[r0 + mt * 16 + 8][e];
            #pragma unroll
            for (int nt = 0; nt < 4; nt++) {
                float2 bias = *(const float2*)(bvec + e * Fdim + wn * 32 + nt * 8 + (lane & 3) * 2);
                out[mt][nt][0] += gA * fmaxf(acc[mt][nt][0] + bias.x, 0.f);
                out[mt][nt][1] += gA * fmaxf(acc[mt][nt][1] + bias.y, 0.f);
                out[mt][nt][2] += gB * fmaxf(acc[mt][nt][2] + bias.x, 0.f);
                out[mt][nt][3] += gB * fmaxf(acc[mt][nt][3] + bias.y, 0.f);
            }
        }
    }

    if (layer == 0) {
        // store fp16 payload p = dinv * result for next layer's gather
        half2* PH2 = (half2*)g_ph;
        #pragma unroll
        for (int mt = 0; mt < 2; mt++) {
            int ra = m0 + r0 + mt * 16;
            int rb = ra + 8;
            #pragma unroll
            for (int nt = 0; nt < 4; nt++) {
                int col = wn * 32 + nt * 8 + (lane & 3) * 2;
                if (ra < Nn) {
                    float da = g_dinv[ra];
                    PH2[((size_t)ra * Fdim + col) >> 1] =
                        __floats2half2_rn(da * out[mt][nt][0], da * out[mt][nt][1]);
                }
                if (rb < Nn) {
                    float db = g_dinv[rb];
                    PH2[((size_t)rb * Fdim + col) >> 1] =
                        __floats2half2_rn(db * out[mt][nt][2], db * out[mt][nt][3]);
                }
            }
        }
    } else {
        // pool directly: stage tile in smem (reuse dynA), segmented sums -> atomics
        float* sT = (float*)dynA;               // 128x128 f32 = 64KB <= 69.6KB
        __syncthreads();                         // all A-tile reads done
        #pragma unroll
        for (int mt = 0; mt < 2; mt++) {
            int ra = r0 + mt * 16;
            #pragma unroll
            for (int nt = 0; nt < 4; nt++) {
                int col = wn * 32 + nt * 8 + (lane & 3) * 2;
                sT[ra * 128 + col]           = out[mt][nt][0];
                sT[ra * 128 + col + 1]       = out[mt][nt][1];
                sT[(ra + 8) * 128 + col]     = out[mt][nt][2];
                sT[(ra + 8) * 128 + col + 1] = out[mt][nt][3];
            }
        }
        __syncthreads();
        int c = tid & 127;
        int q = tid >> 7;                        // 0..3, 32 rows each
        int rbeg = q * 32;
        float acc = 0.f;
        int curg = -1;
        for (int r = rbeg; r < rbeg + 32; r++) {
            int n = m0 + r;
            if (n >= Nn) break;
            int g = batch[n];
            if (g != curg) {
                if (curg >= 0) atomicAdd(&g_pool[curg * Fdim + c], acc);
                acc = 0.f; curg = g;
            }
            acc += sT[r * 128 + c];
        }
        if (curg >= 0) atomicAdd(&g_pool[curg * Fdim + c], acc);
    }
}

// ---------------- final: mean + linear (batch sorted; counts via binary search) ----------------
__device__ __forceinline__ int lbound(const int* __restrict__ b, int val) {
    int lo = 0, hi = Nn;
    while (lo < hi) { int mid = (lo + hi) >> 1; if (b[mid] < val) lo = mid + 1; else hi = mid; }
    return lo;
}
__global__ __launch_bounds__(128)
void k_final(const int* __restrict__ batch,
             const float* __restrict__ Wf, const float* __restrict__ bf,
             float* __restrict__ out) {
    __shared__ float sp[Fdim];
    int g = blockIdx.x;
    int t = threadIdx.x;
    int lo = lbound(batch, g);
    int hi = lbound(batch, g + 1);
    float cnt = (float)(hi - lo);
    sp[t] = g_pool[g * Fdim + t] / fmaxf(cnt, 1.0f);
    __syncthreads();
    if (t < OUTC) {
        float a = bf[t];
        #pragma unroll 8
        for (int k = 0; k < Fdim; k++) a += sp[k] * Wf[k * OUTC + t];
        out[g * OUTC + t] = a;
    }
}

// ---------------- launch ----------------
extern "C" void kernel_launch(void* const* d_in, const int* in_sizes, int n_in,
                              void* d_out, int out_size) {
    const float* x    = (const float*)d_in[0];
    const float* top  = (const float*)d_in[1];
    const int*   ei   = (const int*)  d_in[2];
    const int*   batch= (const int*)  d_in[3];
    const float* W0   = (const float*)d_in[4];
    const float* b0   = (const float*)d_in[5];
    const float* Wg0  = (const float*)d_in[6];
    const float* W1   = (const float*)d_in[7];
    const float* b1   = (const float*)d_in[8];
    const float* Wg1  = (const float*)d_in[9];
    const float* Wf   = (const float*)d_in[10];
    const float* bf   = (const float*)d_in[11];
    float* out = (float*)d_out;

    const int* src = ei;
    const int* dst = ei + Ee;

    cudaFuncSetAttribute(k_gemm_mma, cudaFuncAttributeMaxDynamicSharedMemorySize, DYN_SMEM);

    // init + W packing, CSR build (+ payload prescale fused into fill)
    k_initw    <<<(Nn + 255) / 256, 256>>>(W0, W1);
    k_count    <<<(Ee + 255) / 256, 256>>>(dst);
    k_scan1    <<<NBLK, SCAN_B>>>();
    k_scan3    <<<(Nn + 255) / 256, 256>>>();
    k_fill_prep<<<(Nn * 32 + 255) / 256, 256>>>(src, dst, (const float4*)x);

    int gw = (Nn * 32 + 255) / 256;
    int gg = (Nn + 127) / 128;

    // layer 0
    k_gather  <<<gw, 256>>>();
    k_gemm_mma<<<gg, 512, DYN_SMEM>>>(0, b0, Wg0, top, batch);

    // layer 1
    k_gather  <<<gw, 256>>>();
    k_gemm_mma<<<gg, 512, DYN_SMEM>>>(1, b1, Wg1, top, batch);

    // final
    k_final<<<Gn, 128>>>(batch, Wf, bf, out);
}

// round 14
// speedup vs baseline: 2.0590x; 1.6500x over previous
#include <cuda_runtime.h>
#include <cuda_bf16.h>
#include <cuda_fp16.h>
#include <cstdint>
#include <math.h>

// Problem constants
#define Nn   50000
#define Ee   800000
#define Fdim 128
#define Gn   64
#define OUTC 64
#define EXPN 3
#define TEMP_INV (1.0f/101.0f)

#define SCAN_B 1024
#define NBLK   ((Nn + SCAN_B - 1) / SCAN_B)

// A-tile smem row stride in bytes (128 bf16 = 256B, padded to 272)
#define AROW 272
#define ABYTES (128 * AROW)       // 34816 (single bf16 copy)
#define DYN_SMEM 65536            // pooling staging 128x128 f32 dominates

// ---------------- device scratch ----------------
__device__ float g_dinv[Nn];
__device__ int   g_degi[Nn];
__device__ int   g_off [Nn + 1];
__device__ int   g_cur [Nn];
__device__ int   g_bsum[NBLK];
__device__ int   g_csr [Ee];
__device__ uint2 g_aggh[(size_t)Nn * 32];    // fp16 aggregated features (4 halves/uint2)
__device__ uint2 g_ph  [(size_t)Nn * 32];    // fp16 payload p = dinv*h
__device__ float g_pool[Gn * Fdim];
// packed W fragments: [e(3)][kk(8)][ntg(16)][lane(32)] -> uint2 {b0,b1}
__device__ uint2 g_wph0[12288];
__device__ uint2 g_wpl0[12288];
__device__ uint2 g_wph1[12288];
__device__ uint2 g_wpl1[12288];

// ---------------- helpers ----------------
__device__ __forceinline__ void split2(float a, float b, uint32_t& hi, uint32_t& lo) {
    __nv_bfloat162 h = __floats2bfloat162_rn(a, b);
    float ra = a - __bfloat162float(h.x);
    float rb = b - __bfloat162float(h.y);
    __nv_bfloat162 l = __floats2bfloat162_rn(ra, rb);
    hi = *reinterpret_cast<uint32_t*>(&h);
    lo = *reinterpret_cast<uint32_t*>(&l);
}
__device__ __forceinline__ uint32_t bf2(float a, float b) {
    __nv_bfloat162 h = __floats2bfloat162_rn(a, b);
    return *reinterpret_cast<uint32_t*>(&h);
}
__device__ __forceinline__ uint32_t smem_u32(const void* p) {
    uint32_t a;
    asm("{ .reg .u64 t; cvta.to.shared.u64 t, %1; cvt.u32.u64 %0, t; }" : "=r"(a) : "l"(p));
    return a;
}
__device__ __forceinline__ void ldsm4(uint32_t* r, uint32_t addr) {
    asm volatile("ldmatrix.sync.aligned.m8n8.x4.shared.b16 {%0,%1,%2,%3}, [%4];"
        : "=r"(r[0]), "=r"(r[1]), "=r"(r[2]), "=r"(r[3]) : "r"(addr));
}
__device__ __forceinline__ void mma16816(float* d, const uint32_t* a, uint2 b) {
    asm volatile("mma.sync.aligned.m16n8k16.row.col.f32.bf16.bf16.f32 "
        "{%0,%1,%2,%3}, {%4,%5,%6,%7}, {%8,%9}, {%0,%1,%2,%3};"
        : "+f"(d[0]), "+f"(d[1]), "+f"(d[2]), "+f"(d[3])
        : "r"(a[0]), "r"(a[1]), "r"(a[2]), "r"(a[3]), "r"(b.x), "r"(b.y));
}
__device__ __forceinline__ float4 h4_to_f4(uint2 u) {
    half2 a = *reinterpret_cast<half2*>(&u.x);
    half2 b = *reinterpret_cast<half2*>(&u.y);
    float2 fa = __half22float2(a);
    float2 fb = __half22float2(b);
    return make_float4(fa.x, fa.y, fb.x, fb.y);
}
__device__ __forceinline__ uint2 f4_to_h4(float4 v) {
    half2 h0 = __floats2half2_rn(v.x, v.y);
    half2 h1 = __floats2half2_rn(v.z, v.w);
    uint2 u;
    u.x = *reinterpret_cast<uint32_t*>(&h0);
    u.y = *reinterpret_cast<uint32_t*>(&h1);
    return u;
}

// ---------------- init + W packing (fused) ----------------
__global__ void k_initw(const float* __restrict__ W0, const float* __restrict__ W1) {
    int gidx = blockIdx.x * blockDim.x + threadIdx.x;
    if (gidx < Nn) g_degi[gidx] = 0;
    if (gidx < Gn * Fdim) g_pool[gidx] = 0.f;
    if (gidx < 24576) {
        int layer = (gidx >= 12288) ? 1 : 0;
        int idx   = gidx - layer * 12288;
        int lane = idx & 31;
        int ntg  = (idx >> 5) & 15;
        int kk   = (idx >> 9) & 7;
        int e    = idx >> 12;
        int n  = ntg * 8 + (lane >> 2);
        int k0 = kk * 16 + (lane & 3) * 2;
        const float* We = (layer ? W1 : W0) + (size_t)e * Fdim * Fdim;
        uint32_t h0, l0, h1, l1;
        split2(We[(size_t)k0 * Fdim + n],       We[(size_t)(k0 + 1) * Fdim + n], h0, l0);
        split2(We[(size_t)(k0 + 8) * Fdim + n], We[(size_t)(k0 + 9) * Fdim + n], h1, l1);
        uint2* ph = layer ? g_wph1 : g_wph0;
        uint2* pl = layer ? g_wpl1 : g_wpl0;
        ph[idx] = make_uint2(h0, h1);
        pl[idx] = make_uint2(l0, l1);
    }
}

// ---------------- CSR build ----------------
__global__ void k_count(const int* __restrict__ dst) {
    int e = blockIdx.x * blockDim.x + threadIdx.x;
    if (e < Ee) atomicAdd(&g_degi[dst[e]], 1);
}
__global__ void k_scan1() {      // block scan + fused rsqrt
    __shared__ int s[SCAN_B];
    int b = blockIdx.x, t = threadIdx.x;
    int i = b * SCAN_B + t;
    int v = (i < Nn) ? g_degi[i] : 0;
    if (i < Nn) g_dinv[i] = rsqrtf((float)(v + 1));   // +1 self loop
    s[t] = v;
    __syncthreads();
    for (int d = 1; d < SCAN_B; d <<= 1) {
        int add = (t >= d) ? s[t - d] : 0;
        __syncthreads();
        s[t] += add;
        __syncthreads();
    }
    if (i < Nn) g_off[i] = s[t] - v;
    if (t == SCAN_B - 1) g_bsum[b] = s[t];
}
// scan of block sums done redundantly per block
__global__ void k_scan3() {
    __shared__ int s[64];
    int t = threadIdx.x;
    if (t < 64) s[t] = (t < NBLK) ? g_bsum[t] : 0;
    __syncthreads();
    for (int d = 1; d < 64; d <<= 1) {
        int add = (t < 64 && t >= d) ? s[t - d] : 0;
        __syncthreads();
        if (t < 64) s[t] += add;
        __syncthreads();
    }
    int i = blockIdx.x * blockDim.x + t;
    if (i < Nn) {
        int blk = i / SCAN_B;
        int ex  = (blk == 0) ? 0 : s[blk - 1];
        int o = g_off[i] + ex;
        g_off[i] = o;
        g_cur[i] = o;
    }
    if (i == 0) g_off[Nn] = Ee;
}
// fill CSR (edge threads) + prescale x into fp16 payload (node threads)
__global__ void k_fill_prep(const int* __restrict__ src, const int* __restrict__ dst,
                            const float4* __restrict__ x) {
    int i = blockIdx.x * blockDim.x + threadIdx.x;
    if (i < Ee) {
        int pos = atomicAdd(&g_cur[dst[i]], 1);
        g_csr[pos] = src[i];
    }
    if (i < Nn * 32) {
        int n = i >> 5;
        float d = g_dinv[n];
        float4 v = x[i];
        g_ph[i] = f4_to_h4(make_float4(v.x * d, v.y * d, v.z * d, v.w * d));
    }
}

// ---------------- gather aggregation: one warp per node, pure fp16 row sum ----------------
__global__ __launch_bounds__(256)
void k_gather() {
    int gid  = blockIdx.x * blockDim.x + threadIdx.x;
    int n    = gid >> 5;
    if (n >= Nn) return;
    int lane = gid & 31;
    const uint2* PH = g_ph;
    float4 acc = h4_to_f4(PH[(size_t)n * 32 + lane]);
    int e   = g_off[n];
    int end = g_off[n + 1];
    for (; e + 4 <= end; e += 4) {
        int s0 = g_csr[e],   s1 = g_csr[e+1];
        int s2 = g_csr[e+2], s3 = g_csr[e+3];
        float4 v0 = h4_to_f4(PH[(size_t)s0 * 32 + lane]);
        float4 v1 = h4_to_f4(PH[(size_t)s1 * 32 + lane]);
        float4 v2 = h4_to_f4(PH[(size_t)s2 * 32 + lane]);
        float4 v3 = h4_to_f4(PH[(size_t)s3 * 32 + lane]);
        acc.x += v0.x + v1.x + v2.x + v3.x;
        acc.y += v0.y + v1.y + v2.y + v3.y;
        acc.z += v0.z + v1.z + v2.z + v3.z;
        acc.w += v0.w + v1.w + v2.w + v3.w;
    }
    for (; e < end; e++) {
        int s = g_csr[e];
        float4 vv = h4_to_f4(PH[(size_t)s * 32 + lane]);
        acc.x += vv.x; acc.y += vv.y; acc.z += vv.z; acc.w += vv.w;
    }
    g_aggh[(size_t)n * 32 + lane] = f4_to_h4(acc);
}

// ---------------- MoE GEMM via mma.sync, A in bf16, W exactly split (2 passes) ----------------
// 512 threads, 128-node x 128-col tile. 16 warps: wm = w&3 (32 rows), wn = w>>2 (32 cols).
extern __shared__ char dynA[];
__global__ __launch_bounds__(512)
void k_gemm_mma(int layer,
                const float* __restrict__ bvec, // [3,128]
                const float* __restrict__ Wg,   // [3,4]
                const float* __restrict__ top,  // [N,4]
                const int* __restrict__ batch)  // [N]
{
    __shared__ float sgate[128][4];

    int tid  = threadIdx.x;
    int m0   = blockIdx.x * 128;

    // ---- gates ----
    if (tid < 128) {
        int n = m0 + tid;
        float l0 = 0.f, l1 = 0.f, l2 = 0.f;
        if (n < Nn) {
            float t0 = top[n*4+0], t1 = top[n*4+1], t2 = top[n*4+2], t3 = top[n*4+3];
            l0 = (t0*Wg[0] + t1*Wg[1] + t2*Wg[2]  + t3*Wg[3])  * TEMP_INV;
            l1 = (t0*Wg[4] + t1*Wg[5] + t2*Wg[6]  + t3*Wg[7])  * TEMP_INV;
            l2 = (t0*Wg[8] + t1*Wg[9] + t2*Wg[10] + t3*Wg[11]) * TEMP_INV;
        }
        float mx = fmaxf(l0, fmaxf(l1, l2));
        float e0 = __expf(l0 - mx), e1 = __expf(l1 - mx), e2 = __expf(l2 - mx);
        float inv = 1.0f / (e0 + e1 + e2);
        sgate[tid][0] = e0 * inv; sgate[tid][1] = e1 * inv; sgate[tid][2] = e2 * inv;
    }

    // ---- A tile: dinv*agg(fp16) -> bf16 in smem (single copy) ----
    for (int idx = tid; idx < 4096; idx += 512) {       // 128 rows x 32 uint2
        int row = idx >> 5;
        int u   = idx & 31;
        int n   = m0 + row;
        float4 v = make_float4(0.f, 0.f, 0.f, 0.f);
        if (n < Nn) {
            v = h4_to_f4(g_aggh[(size_t)n * 32 + u]);
            float d = g_dinv[n];
            v.x *= d; v.y *= d; v.z *= d; v.w *= d;
        }
        char* base = dynA + row * AROW + u * 8;
        *reinterpret_cast<uint32_t*>(base)     = bf2(v.x, v.y);
        *reinterpret_cast<uint32_t*>(base + 4) = bf2(v.z, v.w);
    }
    __syncthreads();

    int w    = tid >> 5;
    int lane = tid & 31;
    int wm   = w & 3;
    int wn   = w >> 2;

    uint32_t aBase  = smem_u32(dynA);
    uint32_t aAddr0 = aBase + (uint32_t)(wm * 32 + (lane & 15)) * AROW + (uint32_t)(lane >> 4) * 16;

    const uint2* wph = layer ? g_wph1 : g_wph0;
    const uint2* wpl = layer ? g_wpl1 : g_wpl0;

    float out[2][4][4];
    #pragma unroll
    for (int mt = 0; mt < 2; mt++)
        #pragma unroll
        for (int nt = 0; nt < 4; nt++)
            #pragma unroll
            for (int rr = 0; rr < 4; rr++) out[mt][nt][rr] = 0.f;

    int r0 = wm * 32 + (lane >> 2);

    for (int e = 0; e < EXPN; e++) {
        float acc[2][4][4];
        #pragma unroll
        for (int mt = 0; mt < 2; mt++)
            #pragma unroll
            for (int nt = 0; nt < 4; nt++)
                #pragma unroll
                for (int rr = 0; rr < 4; rr++) acc[mt][nt][rr] = 0.f;

        const uint2* Bh = wph + e * 4096 + (wn * 4) * 32 + lane;
        const uint2* Bl = wpl + e * 4096 + (wn * 4) * 32 + lane;
        #pragma unroll
        for (int kk = 0; kk < 8; kk++) {
            uint32_t a0[4], a1[4];
            ldsm4(a0, aAddr0 + kk * 32);
            ldsm4(a1, aAddr0 + kk * 32 + 16 * AROW);
            const uint2* Bhk = Bh + kk * 512;
            const uint2* Blk = Bl + kk * 512;
            #pragma unroll
            for (int nt = 0; nt < 4; nt++) {
                uint2 bh = Bhk[nt * 32];
                uint2 bl = Blk[nt * 32];
                mma16816(acc[0][nt], a0, bh);
                mma16816(acc[1][nt], a1, bh);
                mma16816(acc[0][nt], a0, bl);
                mma16816(acc[1][nt], a1, bl);
            }
        }
        #pragma unroll
        for (int mt = 0; mt < 2; mt++) {
            float gA = sgate[r0 + mt * 16][e];
            float gB = sgate[r0 + mt * 16 + 8][e];
            #pragma unroll
            for (int nt = 0; nt < 4; nt++) {
                float2 bias = *(const float2*)(bvec + e * Fdim + wn * 32 + nt * 8 + (lane & 3) * 2);
                out[mt][nt][0] += gA * fmaxf(acc[mt][nt][0] + bias.x, 0.f);
                out[mt][nt][1] += gA * fmaxf(acc[mt][nt][1] + bias.y, 0.f);
                out[mt][nt][2] += gB * fmaxf(acc[mt][nt][2] + bias.x, 0.f);
                out[mt][nt][3] += gB * fmaxf(acc[mt][nt][3] + bias.y, 0.f);
            }
        }
    }

    if (layer == 0) {
        // store fp16 payload p = dinv * result for next layer's gather
        half2* PH2 = (half2*)g_ph;
        #pragma unroll
        for (int mt = 0; mt < 2; mt++) {
            int ra = m0 + r0 + mt * 16;
            int rb = ra + 8;
            #pragma unroll
            for (int nt = 0; nt < 4; nt++) {
                int col = wn * 32 + nt * 8 + (lane & 3) * 2;
                if (ra < Nn) {
                    float da = g_dinv[ra];
                    PH2[((size_t)ra * Fdim + col) >> 1] =
                        __floats2half2_rn(da * out[mt][nt][0], da * out[mt][nt][1]);
                }
                if (rb < Nn) {
                    float db = g_dinv[rb];
                    PH2[((size_t)rb * Fdim + col) >> 1] =
                        __floats2half2_rn(db * out[mt][nt][2], db * out[mt][nt][3]);
                }
            }
        }
    } else {
        // pool directly: stage tile in smem, segmented sums -> atomics
        float* sT = (float*)dynA;               // 128x128 f32 = 64KB
        __syncthreads();                         // all A-tile reads done
        #pragma unroll
        for (int mt = 0; mt < 2; mt++) {
            int ra = r0 + mt * 16;
            #pragma unroll
            for (int nt = 0; nt < 4; nt++) {
                int col = wn * 32 + nt * 8 + (lane & 3) * 2;
                sT[ra * 128 + col]           = out[mt][nt][0];
                sT[ra * 128 + col + 1]       = out[mt][nt][1];
                sT[(ra + 8) * 128 + col]     = out[mt][nt][2];
                sT[(ra + 8) * 128 + col + 1] = out[mt][nt][3];
            }
        }
        __syncthreads();
        int c = tid & 127;
        int q = tid >> 7;                        // 0..3, 32 rows each
        int rbeg = q * 32;
        float acc = 0.f;
        int curg = -1;
        for (int r = rbeg; r < rbeg + 32; r++) {
            int n = m0 + r;
            if (n >= Nn) break;
            int g = batch[n];
            if (g != curg) {
                if (curg >= 0) atomicAdd(&g_pool[curg * Fdim + c], acc);
                acc = 0.f; curg = g;
            }
            acc += sT[r * 128 + c];
        }
        if (curg >= 0) atomicAdd(&g_pool[curg * Fdim + c], acc);
    }
}

// ---------------- final: mean + linear (batch sorted; counts via binary search) ----------------
__device__ __forceinline__ int lbound(const int* __restrict__ b, int val) {
    int lo = 0, hi = Nn;
    while (lo < hi) { int mid = (lo + hi) >> 1; if (b[mid] < val) lo = mid + 1; else hi = mid; }
    return lo;
}
__global__ __launch_bounds__(128)
void k_final(const int* __restrict__ batch,
             const float* __restrict__ Wf, const float* __restrict__ bf,
             float* __restrict__ out) {
    __shared__ float sp[Fdim];
    int g = blockIdx.x;
    int t = threadIdx.x;
    int lo = lbound(batch, g);
    int hi = lbound(batch, g + 1);
    float cnt = (float)(hi - lo);
    sp[t] = g_pool[g * Fdim + t] / fmaxf(cnt, 1.0f);
    __syncthreads();
    if (t < OUTC) {
        float a = bf[t];
        #pragma unroll 8
        for (int k = 0; k < Fdim; k++) a += sp[k] * Wf[k * OUTC + t];
        out[g * OUTC + t] = a;
    }
}

// ---------------- launch ----------------
extern "C" void kernel_launch(void* const* d_in, const int* in_sizes, int n_in,
                              void* d_out, int out_size) {
    const float* x    = (const float*)d_in[0];
    const float* top  = (const float*)d_in[1];
    const int*   ei   = (const int*)  d_in[2];
    const int*   batch= (const int*)  d_in[3];
    const float* W0   = (const float*)d_in[4];
    const float* b0   = (const float*)d_in[5];
    const float* Wg0  = (const float*)d_in[6];
    const float* W1   = (const float*)d_in[7];
    const float* b1   = (const float*)d_in[8];
    const float* Wg1  = (const float*)d_in[9];
    const float* Wf   = (const float*)d_in[10];
    const float* bf   = (const float*)d_in[11];
    float* out = (float*)d_out;

    const int* src = ei;
    const int* dst = ei + Ee;

    cudaFuncSetAttribute(k_gemm_mma, cudaFuncAttributeMaxDynamicSharedMemorySize, DYN_SMEM);

    // init + W packing, CSR build (+ payload prescale fused into fill)
    k_initw    <<<(Nn + 255) / 256, 256>>>(W0, W1);
    k_count    <<<(Ee + 255) / 256, 256>>>(dst);
    k_scan1    <<<NBLK, SCAN_B>>>();
    k_scan3    <<<(Nn + 255) / 256, 256>>>();
    k_fill_prep<<<(Nn * 32 + 255) / 256, 256>>>(src, dst, (const float4*)x);

    int gw = (Nn * 32 + 255) / 256;
    int gg = (Nn + 127) / 128;

    // layer 0
    k_gather  <<<gw, 256>>>();
    k_gemm_mma<<<gg, 512, DYN_SMEM>>>(0, b0, Wg0, top, batch);

    // layer 1
    k_gather  <<<gw, 256>>>();
    k_gemm_mma<<<gg, 512, DYN_SMEM>>>(1, b1, Wg1, top, batch);

    // final
    k_final<<<Gn, 128>>>(batch, Wf, bf, out);
}